// round 10
// baseline (speedup 1.0000x reference)
#include <cuda_runtime.h>

#define NT 320            // K1 threads/block
#define PTS_PER_BLOCK 640 // 2 points per thread

// ---- K1 shared-memory layout (floats): view-phase weights + g1 park ----
#define S_W1T   0        // [105][64]  bw1 transposed  (6720)
#define S_B1    6720     // [64]
#define S_W2T   6784     // [64][32]   bw2 transposed  (2048)
#define S_B2    8832     // [32]
#define S_V1T   8864     // [32][32]   vw1 transposed, pre-scaled by 1/3 (1024)
#define S_VB1   9888     // [32]
#define S_V2T   9920     // [32][32]   vw2 transposed (1024)
#define S_VB2   10944    // [32]
#define S_WEND  10976
#define S_G1    10976    // g1 park: 64 ull slots x 320 threads = 40960 floats
#define S_TOT   (10976 + 40960)
#define SMEM1_BYTES (S_TOT * 4)    // 207744 B -> 1 block/SM

// ---- K2 shared-memory layout (floats): head weights ----
#define H_R1T   0        // [96][32] rw1 transposed (3072)
#define H_RB1   3072
#define H_R2T   3104     // [32][16] rw2 transposed (512)
#define H_RB2   3616
#define H_RW3   3632     // [3][16]
#define H_RB3   3680     // [4]
#define H_TOT   3684
#define SMEM2_BYTES (H_TOT * 4)

#define P_CONST 524288

typedef unsigned long long ull;

// global scratch (module-static; allocation-free at kernel time)
__device__ float g_scr[(size_t)P_CONST * 105];     // input, interleaved [P/32][105][32]
__device__ ull   x_scr[(size_t)48 * P_CONST];      // x per view: slot (v*16+j) of point p at [slot*P + p]

__device__ __forceinline__ float elu1(float x) {
    return x > 0.f ? x : (__expf(x) - 1.f);
}
__device__ __forceinline__ void ffma2(ull &d, ull a, ull b) {
    asm("fma.rn.f32x2 %0, %1, %2, %0;" : "+l"(d) : "l"(a), "l"(b));
}
__device__ __forceinline__ ull bcast2(float c) {
    ull v; asm("mov.b64 %0, {%1, %2};" : "=l"(v) : "f"(c), "f"(c)); return v;
}
__device__ __forceinline__ ull pack2(float lo, float hi) {
    ull v; asm("mov.b64 %0, {%1, %2};" : "=l"(v) : "f"(lo), "f"(hi)); return v;
}
__device__ __forceinline__ void unpack2(ull v, float &lo, float &hi) {
    asm("mov.b64 {%0, %1}, %2;" : "=f"(lo), "=f"(hi) : "l"(v));
}

// dual-point FMA row (1 LDS.128 : 4 FFMA2)
template<int OUT>
__device__ __forceinline__ void fma_row2(ull* a, ull* b, const float* row, ull ca, ull cb) {
    const ulonglong2* wp = reinterpret_cast<const ulonglong2*>(row);
#pragma unroll
    for (int q = 0; q < OUT / 4; ++q) {
        ulonglong2 w = wp[q];
        ffma2(a[2 * q],     ca, w.x);
        ffma2(b[2 * q],     cb, w.x);
        ffma2(a[2 * q + 1], ca, w.y);
        ffma2(b[2 * q + 1], cb, w.y);
    }
}
template<int OUT>
__device__ __forceinline__ void load_bias2(ull* a, ull* b, const float* bp_) {
    const ulonglong2* bp = reinterpret_cast<const ulonglong2*>(bp_);
#pragma unroll
    for (int q = 0; q < OUT / 4; ++q) {
        ulonglong2 w = bp[q];
        a[2 * q] = w.x; a[2 * q + 1] = w.y;
        b[2 * q] = w.x; b[2 * q + 1] = w.y;
    }
}
// single-point variants (K2)
template<int OUT>
__device__ __forceinline__ void fma_row(ull* acc, const float* row, ull c2) {
    const ulonglong2* wp = reinterpret_cast<const ulonglong2*>(row);
#pragma unroll
    for (int q = 0; q < OUT / 4; ++q) {
        ulonglong2 w = wp[q];
        ffma2(acc[2 * q],     c2, w.x);
        ffma2(acc[2 * q + 1], c2, w.y);
    }
}
template<int OUT>
__device__ __forceinline__ void load_bias(ull* acc, const float* b) {
    const ulonglong2* bp = reinterpret_cast<const ulonglong2*>(b);
#pragma unroll
    for (int q = 0; q < OUT / 4; ++q) {
        ulonglong2 w = bp[q];
        acc[2 * q]     = w.x;
        acc[2 * q + 1] = w.y;
    }
}

// ================= K0: transpose input to [P/32][105][32] + emit rgb_in ==========
__global__ __launch_bounds__(256, 4)
void k_prep(const float* __restrict__ rgb, float* __restrict__ out_in, int P)
{
    __shared__ float st[32 * 105];
    const int g = blockIdx.x;
    const int tid = threadIdx.x;

    const float4* src4 = reinterpret_cast<const float4*>(rgb + (size_t)g * 3360);
    float4* st4 = reinterpret_cast<float4*>(st);
#pragma unroll
    for (int i = tid; i < 840; i += 256) st4[i] = src4[i];
    __syncthreads();

    float* dst = g_scr + (size_t)g * 3360;
#pragma unroll
    for (int i = tid; i < 3360; i += 256) {
        int j = i >> 5, lane = i & 31;
        dst[i] = st[lane * 105 + j];
    }
    for (int i = tid; i < 288; i += 256) {
        int pl = i / 9, r = i % 9, v = r / 3, k = r % 3;
        out_in[((size_t)g * 32 + pl) * 9 + r] = st[pl * 105 + v * 35 + k];
    }
}

// ====== K1: g1 + per-view MLP -> x, 2 points/thread, 320 thr, 10 warps/SM ========
__global__ __launch_bounds__(NT, 1)
void k_main(
    const float* __restrict__ bw1, const float* __restrict__ bb1,
    const float* __restrict__ bw2, const float* __restrict__ bb2,
    const float* __restrict__ vw1, const float* __restrict__ vb1,
    const float* __restrict__ vw2, const float* __restrict__ vb2,
    int P)
{
    extern __shared__ float s[];
    const int tid = threadIdx.x;

    // ---- stage weights (transposed) ----
    for (int i = tid; i < 6720; i += NT) { int k = i >> 6, j = i & 63; s[S_W1T + i] = bw1[j * 105 + k]; }
    for (int i = tid; i < 64;   i += NT) s[S_B1 + i] = bb1[i];
    for (int i = tid; i < 2048; i += NT) { int k = i >> 5, j = i & 31; s[S_W2T + i] = bw2[j * 64 + k]; }
    for (int i = tid; i < 32;   i += NT) s[S_B2 + i] = bb2[i];
    for (int i = tid; i < 1024; i += NT) { int k = i >> 5, j = i & 31; s[S_V1T + i] = vw1[j * 32 + k] * (1.f / 3.f); }
    for (int i = tid; i < 32;   i += NT) s[S_VB1 + i] = vb1[i];
    for (int i = tid; i < 1024; i += NT) { int k = i >> 5, j = i & 31; s[S_V2T + i] = vw2[j * 32 + k]; }
    for (int i = tid; i < 32;   i += NT) s[S_VB2 + i] = vb2[i];
    __syncthreads();

    const int lane = tid & 31;
    const int w    = tid >> 5;                 // warp in block (0..9)
    const int p0 = blockIdx.x * PTS_PER_BLOCK + tid;
    const int p1 = p0 + NT;
    const bool okA = (p0 < P);
    const bool okB = (p1 < P);
    // input: element j of point p at g_scr[(p>>5)*3360 + j*32 + (p&31)]
    const float* fA = okA ? (g_scr + (size_t)(blockIdx.x * 20 + w) * 3360 + lane) : (g_scr + lane);
    const float* fB = okB ? (g_scr + (size_t)(blockIdx.x * 20 + 10 + w) * 3360 + lane) : fA;
#define FA(j) __ldg(fA + (j) * 32)
#define FB(j) __ldg(fB + (j) * 32)

    ull* g1s = reinterpret_cast<ull*>(s + S_G1);   // slot j at g1s[j*NT + tid]

    // ---- phase 0: stats + g1 in 32-neuron halves; park in SMEM ----
#pragma unroll 1
    for (int h = 0; h < 2; ++h) {
        ull ga[16], gb[16];
        load_bias2<32>(ga, gb, s + S_B1 + h * 32);
#pragma unroll 5
        for (int k = 0; k < 35; ++k) {
            float aA = FA(k), bA = FA(35 + k), cA = FA(70 + k);
            float aB = FB(k), bB = FB(35 + k), cB = FB(70 + k);
            float mA = (aA + bA + cA) * (1.f / 3.f);
            float mB = (aB + bB + cB) * (1.f / 3.f);
            float qA = fmaf(-mA, mA, fmaf(aA, aA, fmaf(bA, bA, cA * cA)) * (1.f / 3.f));
            float qB = fmaf(-mB, mB, fmaf(aB, aB, fmaf(bB, bB, cB * cB)) * (1.f / 3.f));
            fma_row2<32>(ga, gb, s + S_W1T + k * 64 + h * 32,        bcast2(mA), bcast2(mB));
            fma_row2<32>(ga, gb, s + S_W1T + (35 + k) * 64 + h * 32, bcast2(qA), bcast2(qB));
        }
#pragma unroll
        for (int j = 0; j < 16; ++j) {
            g1s[(h * 16 + j) * NT + tid]        = ga[j];
            g1s[(32 + h * 16 + j) * NT + tid]   = gb[j];
        }
    }

    // ---- per-view MLP -> x streamed to global ----
#pragma unroll 1
    for (int v = 0; v < 3; ++v) {
        ull h2a[16], h2b[16];
        load_bias2<32>(h2a, h2b, s + S_B2);

        // layer1 in 32-neuron halves (init from parked g1), feeding layer2
#pragma unroll 1
        for (int h = 0; h < 2; ++h) {
            ull h1a[16], h1b[16];
#pragma unroll
            for (int j = 0; j < 16; ++j) {
                h1a[j] = g1s[(h * 16 + j) * NT + tid];
                h1b[j] = g1s[(32 + h * 16 + j) * NT + tid];
            }
#pragma unroll 5
            for (int k = 0; k < 35; ++k) {
                float ca = FA(v * 35 + k), cb = FB(v * 35 + k);
                fma_row2<32>(h1a, h1b, s + S_W1T + (70 + k) * 64 + h * 32,
                             bcast2(ca), bcast2(cb));
            }
            // layer2 partial: rows h*32 .. h*32+31 consume elu(h1)
#pragma unroll
            for (int i = 0; i < 16; ++i) {
                float alo, ahi, blo, bhi;
                unpack2(h1a[i], alo, ahi);
                unpack2(h1b[i], blo, bhi);
                fma_row2<32>(h2a, h2b, s + S_W2T + (h * 32 + 2 * i) * 32,
                             bcast2(elu1(alo)), bcast2(elu1(blo)));
                fma_row2<32>(h2a, h2b, s + S_W2T + (h * 32 + 2 * i + 1) * 32,
                             bcast2(elu1(ahi)), bcast2(elu1(bhi)));
            }
        }
        // h2e = elu(h2) in place
#pragma unroll
        for (int i = 0; i < 16; ++i) {
            float lo, hi;
            unpack2(h2a[i], lo, hi); h2a[i] = pack2(elu1(lo), elu1(hi));
            unpack2(h2b[i], lo, hi); h2b[i] = pack2(elu1(lo), elu1(hi));
        }

        // t1 = vb1 + (vw1/3) @ h2e ; t1 = elu(t1)
        ull t1a[16], t1b[16];
        load_bias2<32>(t1a, t1b, s + S_VB1);
#pragma unroll
        for (int i = 0; i < 16; ++i) {
            float alo, ahi, blo, bhi;
            unpack2(h2a[i], alo, ahi);
            unpack2(h2b[i], blo, bhi);
            fma_row2<32>(t1a, t1b, s + S_V1T + (2 * i) * 32,     bcast2(alo), bcast2(blo));
            fma_row2<32>(t1a, t1b, s + S_V1T + (2 * i + 1) * 32, bcast2(ahi), bcast2(bhi));
        }
#pragma unroll
        for (int i = 0; i < 16; ++i) {
            float lo, hi;
            unpack2(t1a[i], lo, hi); t1a[i] = pack2(elu1(lo), elu1(hi));
            unpack2(t1b[i], lo, hi); t1b[i] = pack2(elu1(lo), elu1(hi));
        }

        // t2 in 8-neuron quarters; x = h2e + elu(t2) overwrites h2 in place
#pragma unroll 1
        for (int q = 0; q < 4; ++q) {
            ull t2a[4], t2b[4];
            load_bias2<8>(t2a, t2b, s + S_VB2 + q * 8);
#pragma unroll
            for (int i = 0; i < 16; ++i) {
                float alo, ahi, blo, bhi;
                unpack2(t1a[i], alo, ahi);
                unpack2(t1b[i], blo, bhi);
                fma_row2<8>(t2a, t2b, s + S_V2T + (2 * i) * 32 + q * 8,     bcast2(alo), bcast2(blo));
                fma_row2<8>(t2a, t2b, s + S_V2T + (2 * i + 1) * 32 + q * 8, bcast2(ahi), bcast2(bhi));
            }
#pragma unroll
            for (int u = 0; u < 4; ++u) {
                float tlo, thi, hlo, hhi;
                unpack2(t2a[u], tlo, thi);
                unpack2(h2a[q * 4 + u], hlo, hhi);
                h2a[q * 4 + u] = pack2(hlo + elu1(tlo), hhi + elu1(thi));
                unpack2(t2b[u], tlo, thi);
                unpack2(h2b[q * 4 + u], hlo, hhi);
                h2b[q * 4 + u] = pack2(hlo + elu1(tlo), hhi + elu1(thi));
            }
        }

        // stream x to global (write-only; consumed by K2)
        if (okA) {
#pragma unroll
            for (int j = 0; j < 16; ++j)
                x_scr[(size_t)(v * 16 + j) * P_CONST + p0] = h2a[j];
        }
        if (okB) {
#pragma unroll
            for (int j = 0; j < 16; ++j)
                x_scr[(size_t)(v * 16 + j) * P_CONST + p1] = h2b[j];
        }
    }
#undef FA
#undef FB
}

// ================= K2: head 96->32->16->3 + sigmoid, 1 point/thread ==============
__global__ __launch_bounds__(256, 4)
void k_head(
    const float* __restrict__ rw1, const float* __restrict__ rb1,
    const float* __restrict__ rw2, const float* __restrict__ rb2,
    const float* __restrict__ rw3, const float* __restrict__ rb3,
    float* __restrict__ out_rgb, int P)
{
    __shared__ float s[H_TOT];
    const int tid = threadIdx.x;

    for (int i = tid; i < 3072; i += 256) { int k = i >> 5, j = i & 31; s[H_R1T + i] = rw1[j * 96 + k]; }
    for (int i = tid; i < 32;   i += 256) s[H_RB1 + i] = rb1[i];
    for (int i = tid; i < 512;  i += 256) { int k = i >> 4, j = i & 15; s[H_R2T + i] = rw2[j * 32 + k]; }
    for (int i = tid; i < 16;   i += 256) s[H_RB2 + i] = rb2[i];
    for (int i = tid; i < 48;   i += 256) s[H_RW3 + i] = rw3[i];
    for (int i = tid; i < 4;    i += 256) s[H_RB3 + i] = (i < 3) ? rb3[i] : 0.f;
    __syncthreads();

    const int p = blockIdx.x * 256 + tid;

    // r1 = rb1 + rw1 @ x  (x streamed from global, coalesced, per view)
    ull r1[16];
    load_bias<32>(r1, s + H_RB1);
#pragma unroll 1
    for (int v = 0; v < 3; ++v) {
        ull xv[16];
#pragma unroll
        for (int j = 0; j < 16; ++j)
            xv[j] = x_scr[(size_t)(v * 16 + j) * P_CONST + p];   // independent LDGs
#pragma unroll
        for (int i = 0; i < 16; ++i) {
            float lo, hi; unpack2(xv[i], lo, hi);
            fma_row<32>(r1, s + H_R1T + (v * 32 + 2 * i) * 32,     bcast2(lo));
            fma_row<32>(r1, s + H_R1T + (v * 32 + 2 * i + 1) * 32, bcast2(hi));
        }
    }

    // r2 = rb2 + rw2 @ elu(r1)
    ull r2[8];
    load_bias<16>(r2, s + H_RB2);
#pragma unroll
    for (int i = 0; i < 16; ++i) {
        float lo, hi; unpack2(r1[i], lo, hi);
        fma_row<16>(r2, s + H_R2T + (2 * i) * 16,     bcast2(elu1(lo)));
        fma_row<16>(r2, s + H_R2T + (2 * i + 1) * 16, bcast2(elu1(hi)));
    }
    float r2e[16];
#pragma unroll
    for (int i = 0; i < 8; ++i) {
        float lo, hi; unpack2(r2[i], lo, hi);
        r2e[2 * i]     = elu1(lo);
        r2e[2 * i + 1] = elu1(hi);
    }
#pragma unroll
    for (int c = 0; c < 3; ++c) {
        float a = s[H_RB3 + c];
#pragma unroll
        for (int k = 0; k < 16; ++k)
            a = fmaf(r2e[k], s[H_RW3 + c * 16 + k], a);
        out_rgb[(size_t)p * 3 + c] = 1.f / (1.f + __expf(-a));
    }
}

extern "C" void kernel_launch(void* const* d_in, const int* in_sizes, int n_in,
                              void* d_out, int out_size)
{
    const float* rgb = (const float*)d_in[0];
    const float* bw1 = (const float*)d_in[1];
    const float* bb1 = (const float*)d_in[2];
    const float* bw2 = (const float*)d_in[3];
    const float* bb2 = (const float*)d_in[4];
    const float* vw1 = (const float*)d_in[5];
    const float* vb1 = (const float*)d_in[6];
    const float* vw2 = (const float*)d_in[7];
    const float* vb2 = (const float*)d_in[8];
    const float* rw1 = (const float*)d_in[9];
    const float* rb1 = (const float*)d_in[10];
    const float* rw2 = (const float*)d_in[11];
    const float* rb2 = (const float*)d_in[12];
    const float* rw3 = (const float*)d_in[13];
    const float* rb3 = (const float*)d_in[14];

    const int P = in_sizes[0] / 105;                  // 524288
    float* out_in  = (float*)d_out;                   // rgb_in : P*9
    float* out_rgb = (float*)d_out + (size_t)P * 9;   // rgb_out: P*3

    // K0: input transpose + rgb_in
    k_prep<<<P / 32, 256>>>(rgb, out_in, P);

    // K1: g1 + views -> x
    cudaFuncSetAttribute(k_main, cudaFuncAttributeMaxDynamicSharedMemorySize, SMEM1_BYTES);
    k_main<<<(P + PTS_PER_BLOCK - 1) / PTS_PER_BLOCK, NT, SMEM1_BYTES>>>(
        bw1, bb1, bw2, bb2, vw1, vb1, vw2, vb2, P);

    // K2: head
    k_head<<<P / 256, 256>>>(rw1, rb1, rw2, rb2, rw3, rb3, out_rgb, P);
}

// round 12
// speedup vs baseline: 3.6881x; 3.6881x over previous
#include <cuda_runtime.h>
#include <cuda_bf16.h>
#include <cstdint>

#define P_CONST 524288

// ---- bias float indices in sf[] ----
#define SF_BB1  0
#define SF_BB2  64
#define SF_VB1  96
#define SF_VB2  128
#define SF_RB1  160
#define SF_RB2  192
#define SF_RW3  208
#define SF_RB3  256

// ---- smem byte offsets ----
#define BW1A 1152u               // 40 tiles (8nt x 5kt)
#define BW1B (BW1A + 40u*512u)   // 24 tiles (8nt x 3kt)
#define BW2  (BW1B + 24u*512u)   // 16 tiles (4x4)
#define BV1  (BW2  + 16u*512u)   // 8 tiles  (4x2)
#define BV2  (BV1  +  8u*512u)   // 8 tiles
#define BR1  (BV2  +  8u*512u)   // 24 tiles (3 views x 4x2)
#define BR2  (BR1  + 24u*512u)   // 4 tiles  (2x2)
#define AWBASE (BR2 + 4u*512u)   // per-warp A1 staging, 9216B each
// per warp: A1a hi[16x88 bf16]=2816, A1a lo=2816, A1b hi[16x56]=1792, A1b lo=1792
#define HSBASE (AWBASE + 4u*9216u)   // per-warp head scratch 1024B
#define SMEM_TC (HSBASE + 4u*1024u)

__device__ float g_scr[(size_t)P_CONST * 105];   // input transposed [P/32][105][32]

// ========================= helpers =========================
__device__ __forceinline__ float elu1(float x) {
    return x > 0.f ? x : (__expf(x) - 1.f);
}
__device__ __forceinline__ void bsplit(float x, __nv_bfloat16 &h, __nv_bfloat16 &l) {
    h = __float2bfloat16(x);
    l = __float2bfloat16(x - __bfloat162float(h));
}
__device__ __forceinline__ uint32_t bpack(__nv_bfloat16 a, __nv_bfloat16 b) {
    __nv_bfloat162 t(a, b);    // .x = a = low half = first element
    return *reinterpret_cast<uint32_t*>(&t);
}
// pack two fp32 (cols c, c+1) into hi/lo bf16x2 regs
__device__ __forceinline__ void pack_hl(float x, float y, uint32_t &hi, uint32_t &lo) {
    __nv_bfloat16 hx, lx, hy, ly;
    bsplit(x, hx, lx); bsplit(y, hy, ly);
    hi = bpack(hx, hy); lo = bpack(lx, ly);
}

// mma.m16n8k16 row.col f32 += bf16*bf16
__device__ __forceinline__ void mma_bf(float* d, const uint32_t* a, uint32_t b0, uint32_t b1) {
    asm volatile(
        "mma.sync.aligned.m16n8k16.row.col.f32.bf16.bf16.f32 "
        "{%0,%1,%2,%3}, {%4,%5,%6,%7}, {%8,%9}, {%0,%1,%2,%3};"
        : "+f"(d[0]), "+f"(d[1]), "+f"(d[2]), "+f"(d[3])
        : "r"(a[0]), "r"(a[1]), "r"(a[2]), "r"(a[3]), "r"(b0), "r"(b1));
}
// 3-term split product: D += Ah*Bh + Al*Bh + Ah*Bl
__device__ __forceinline__ void mma3(float* d, const uint32_t* ah, const uint32_t* al, uint4 bt) {
    mma_bf(d, ah, bt.x, bt.y);
    mma_bf(d, al, bt.x, bt.y);
    mma_bf(d, ah, bt.z, bt.w);
}
// A fragment from smem bf16 matrix [16 x cols], row stride rs bytes
__device__ __forceinline__ void load_afrag(uint32_t* a, const char* sb, uint32_t base,
                                           int rs, int col0, int g) {
    a[0] = *reinterpret_cast<const uint32_t*>(sb + base + g * rs + col0 * 2);
    a[1] = *reinterpret_cast<const uint32_t*>(sb + base + (g + 8) * rs + col0 * 2);
    a[2] = *reinterpret_cast<const uint32_t*>(sb + base + g * rs + (col0 + 8) * 2);
    a[3] = *reinterpret_cast<const uint32_t*>(sb + base + (g + 8) * rs + (col0 + 8) * 2);
}
// D init from bias (cols nt*8+t*2, +1; rows share bias)
__device__ __forceinline__ void dinit(float* d, const float* sf, int boff, int nt, int t) {
    float b0 = sf[boff + nt * 8 + t * 2];
    float b1 = sf[boff + nt * 8 + t * 2 + 1];
    d[0] = b0; d[1] = b1; d[2] = b0; d[3] = b1;
}
// chain: two D tiles (2kt, 2kt+1) -> next-layer A fragment, applying f(x)
__device__ __forceinline__ void pack_frag_elu(const float* dA, const float* dB,
                                              uint32_t* ah, uint32_t* al) {
    pack_hl(elu1(dA[0]), elu1(dA[1]), ah[0], al[0]);
    pack_hl(elu1(dA[2]), elu1(dA[3]), ah[1], al[1]);
    pack_hl(elu1(dB[0]), elu1(dB[1]), ah[2], al[2]);
    pack_hl(elu1(dB[2]), elu1(dB[3]), ah[3], al[3]);
}
__device__ __forceinline__ void pack_frag_raw(const float* dA, const float* dB,
                                              uint32_t* ah, uint32_t* al) {
    pack_hl(dA[0], dA[1], ah[0], al[0]);
    pack_hl(dA[2], dA[3], ah[1], al[1]);
    pack_hl(dB[0], dB[1], ah[2], al[2]);
    pack_hl(dB[2], dB[3], ah[3], al[3]);
}

// stage weight matrix w[N][K] (row stride ldw floats) as fragment-packed B tiles
__device__ void stage_B(char* sb, uint32_t off, const float* __restrict__ w,
                        int N, int K, int ldw, float scale, int NT, int KT,
                        int wid, int lane) {
    int g = lane >> 2, t = lane & 3;
    for (int tile = wid; tile < NT * KT; tile += 4) {
        int kt = tile / NT, nt = tile % NT;
        int n = nt * 8 + g;
        int k0 = kt * 16 + t * 2;
        float v0 = 0.f, v1 = 0.f, v2 = 0.f, v3 = 0.f;
        if (n < N) {
            if (k0 < K)     v0 = __ldg(w + n * ldw + k0) * scale;
            if (k0 + 1 < K) v1 = __ldg(w + n * ldw + k0 + 1) * scale;
            if (k0 + 8 < K) v2 = __ldg(w + n * ldw + k0 + 8) * scale;
            if (k0 + 9 < K) v3 = __ldg(w + n * ldw + k0 + 9) * scale;
        }
        __nv_bfloat16 h0, l0, h1, l1, h2, l2, h3, l3;
        bsplit(v0, h0, l0); bsplit(v1, h1, l1);
        bsplit(v2, h2, l2); bsplit(v3, h3, l3);
        uint4 u;
        u.x = bpack(h0, h1);   // b0 hi (k0, k0+1)
        u.y = bpack(h2, h3);   // b1 hi (k0+8, k0+9)
        u.z = bpack(l0, l1);   // b0 lo
        u.w = bpack(l2, l3);   // b1 lo
        *reinterpret_cast<uint4*>(sb + off + ((uint32_t)tile * 32u + lane) * 16u) = u;
    }
}

// ================= K0: transpose input to [P/32][105][32] + emit rgb_in ==========
__global__ __launch_bounds__(256, 4)
void k_prep(const float* __restrict__ rgb, float* __restrict__ out_in, int P)
{
    __shared__ float st[32 * 105];
    const int g = blockIdx.x;
    const int tid = threadIdx.x;

    const float4* src4 = reinterpret_cast<const float4*>(rgb + (size_t)g * 3360);
    float4* st4 = reinterpret_cast<float4*>(st);
#pragma unroll
    for (int i = tid; i < 840; i += 256) st4[i] = src4[i];
    __syncthreads();

    float* dst = g_scr + (size_t)g * 3360;
#pragma unroll
    for (int i = tid; i < 3360; i += 256) {
        int j = i >> 5, lane = i & 31;
        dst[i] = st[lane * 105 + j];
    }
    for (int i = tid; i < 288; i += 256) {
        int pl = i / 9, r = i % 9, v = r / 3, k = r % 3;
        out_in[((size_t)g * 32 + pl) * 9 + r] = st[pl * 105 + v * 35 + k];
    }
}

// ================= K1: HMMA fragment-chained MLP, persistent ======================
__global__ __launch_bounds__(128)
void k_tc(
    const float* __restrict__ bw1, const float* __restrict__ bb1,
    const float* __restrict__ bw2, const float* __restrict__ bb2,
    const float* __restrict__ vw1, const float* __restrict__ vb1,
    const float* __restrict__ vw2, const float* __restrict__ vb2,
    const float* __restrict__ rw1, const float* __restrict__ rb1,
    const float* __restrict__ rw2, const float* __restrict__ rb2,
    const float* __restrict__ rw3, const float* __restrict__ rb3,
    float* __restrict__ out_rgb, int P)
{
    extern __shared__ char sb[];
    float* sf = reinterpret_cast<float*>(sb);
    const int tid = threadIdx.x;
    const int wid = tid >> 5;
    const int lane = tid & 31;
    const int g = lane >> 2;      // row group 0..7
    const int t = lane & 3;       // thread-in-group 0..3

    // ---- stage biases ----
    for (int i = tid; i < 64; i += 128) sf[SF_BB1 + i] = bb1[i];
    for (int i = tid; i < 32; i += 128) sf[SF_BB2 + i] = bb2[i];
    for (int i = tid; i < 32; i += 128) sf[SF_VB1 + i] = vb1[i];
    for (int i = tid; i < 32; i += 128) sf[SF_VB2 + i] = vb2[i];
    for (int i = tid; i < 32; i += 128) sf[SF_RB1 + i] = rb1[i];
    for (int i = tid; i < 16; i += 128) sf[SF_RB2 + i] = rb2[i];
    for (int i = tid; i < 48; i += 128) sf[SF_RW3 + i] = rw3[i];
    for (int i = tid; i < 3;  i += 128) sf[SF_RB3 + i] = rb3[i];

    // ---- stage fragment-packed weights ----
    stage_B(sb, BW1A, bw1,      64, 70, 105, 1.f,       8, 5, wid, lane);
    stage_B(sb, BW1B, bw1 + 70, 64, 35, 105, 1.f,       8, 3, wid, lane);
    stage_B(sb, BW2,  bw2,      32, 64, 64,  1.f,       4, 4, wid, lane);
    stage_B(sb, BV1,  vw1,      32, 32, 32,  1.f / 3.f, 4, 2, wid, lane);
    stage_B(sb, BV2,  vw2,      32, 32, 32,  1.f,       4, 2, wid, lane);
    for (int v = 0; v < 3; ++v)
        stage_B(sb, BR1 + (uint32_t)v * 8u * 512u, rw1 + v * 32, 32, 32, 96, 1.f, 4, 2, wid, lane);
    stage_B(sb, BR2,  rw2,      16, 32, 32,  1.f,       2, 2, wid, lane);

    // per-warp A1 staging bases
    const uint32_t aw   = AWBASE + (uint32_t)wid * 9216u;
    const uint32_t A1AH = aw, A1AL = aw + 2816u;
    const uint32_t A1BH = aw + 5632u, A1BL = aw + 7424u;
    const uint32_t HS   = HSBASE + (uint32_t)wid * 1024u;

    // zero pads: A1a cols 70..79, A1b cols 35..47 (written once, never touched again)
    for (int i = lane; i < 160; i += 32) {
        int q = i / 10, c = 70 + i % 10;
        *reinterpret_cast<__nv_bfloat16*>(sb + A1AH + q * 176 + c * 2) = __float2bfloat16(0.f);
        *reinterpret_cast<__nv_bfloat16*>(sb + A1AL + q * 176 + c * 2) = __float2bfloat16(0.f);
    }
    for (int i = lane; i < 208; i += 32) {
        int q = i / 13, c = 35 + i % 13;
        *reinterpret_cast<__nv_bfloat16*>(sb + A1BH + q * 112 + c * 2) = __float2bfloat16(0.f);
        *reinterpret_cast<__nv_bfloat16*>(sb + A1BL + q * 112 + c * 2) = __float2bfloat16(0.f);
    }
    __syncthreads();   // staging complete; warps run independently from here

    const int ntile = P / 64;
    for (int tile = blockIdx.x; tile < ntile; tile += gridDim.x) {
        // this warp's 16 points: feature j of local point q at gb[j*32 + q]
        const float* gb = g_scr + (size_t)(tile * 2 + (wid >> 1)) * 3360 + (wid & 1) * 16;

        // ---- stats -> A1a (cols 0..34 mean, 35..69 var) ----
        for (int i = lane; i < 560; i += 32) {
            int q = i & 15, k = i >> 4;
            float a = __ldg(gb + k * 32 + q);
            float b = __ldg(gb + (35 + k) * 32 + q);
            float c = __ldg(gb + (70 + k) * 32 + q);
            float m = (a + b + c) * (1.f / 3.f);
            float qv = fmaf(-m, m, fmaf(a, a, fmaf(b, b, c * c)) * (1.f / 3.f));
            __nv_bfloat16 h, l;
            bsplit(m, h, l);
            *reinterpret_cast<__nv_bfloat16*>(sb + A1AH + q * 176 + k * 2) = h;
            *reinterpret_cast<__nv_bfloat16*>(sb + A1AL + q * 176 + k * 2) = l;
            bsplit(qv, h, l);
            *reinterpret_cast<__nv_bfloat16*>(sb + A1AH + q * 176 + (35 + k) * 2) = h;
            *reinterpret_cast<__nv_bfloat16*>(sb + A1AL + q * 176 + (35 + k) * 2) = l;
        }
        __syncwarp();

        // ---- g1 = bb1 + A1a @ W1a^T  (shared across views) ----
        float g1d[8][4];
#pragma unroll
        for (int nt = 0; nt < 8; ++nt) dinit(g1d[nt], sf, SF_BB1, nt, t);
#pragma unroll
        for (int kt = 0; kt < 5; ++kt) {
            uint32_t ah[4], al[4];
            load_afrag(ah, sb, A1AH, 176, kt * 16 + t * 2, g);
            load_afrag(al, sb, A1AL, 176, kt * 16 + t * 2, g);
#pragma unroll
            for (int nt = 0; nt < 8; ++nt) {
                uint4 bt = *reinterpret_cast<const uint4*>(sb + BW1A + ((kt * 8 + nt) * 32 + lane) * 16);
                mma3(g1d[nt], ah, al, bt);
            }
        }

        float r1d[4][4];
#pragma unroll
        for (int nt = 0; nt < 4; ++nt) dinit(r1d[nt], sf, SF_RB1, nt, t);

        // ---- per-view ----
#pragma unroll 1
        for (int v = 0; v < 3; ++v) {
            // A1b = f_v (cols 0..34)
            for (int i = lane; i < 560; i += 32) {
                int q = i & 15, k = i >> 4;
                float fv = __ldg(gb + (v * 35 + k) * 32 + q);
                __nv_bfloat16 h, l;
                bsplit(fv, h, l);
                *reinterpret_cast<__nv_bfloat16*>(sb + A1BH + q * 112 + k * 2) = h;
                *reinterpret_cast<__nv_bfloat16*>(sb + A1BL + q * 112 + k * 2) = l;
            }
            __syncwarp();

            // L1: d1 = g1 + A1b @ W1b^T
            float d1[8][4];
#pragma unroll
            for (int nt = 0; nt < 8; ++nt)
#pragma unroll
                for (int i = 0; i < 4; ++i) d1[nt][i] = g1d[nt][i];
#pragma unroll
            for (int kt = 0; kt < 3; ++kt) {
                uint32_t ah[4], al[4];
                load_afrag(ah, sb, A1BH, 112, kt * 16 + t * 2, g);
                load_afrag(al, sb, A1BL, 112, kt * 16 + t * 2, g);
#pragma unroll
                for (int nt = 0; nt < 8; ++nt) {
                    uint4 bt = *reinterpret_cast<const uint4*>(sb + BW1B + ((kt * 8 + nt) * 32 + lane) * 16);
                    mma3(d1[nt], ah, al, bt);
                }
            }
            // chain: A2 = elu(d1)
            uint32_t a2h[4][4], a2l[4][4];
#pragma unroll
            for (int k2 = 0; k2 < 4; ++k2)
                pack_frag_elu(d1[2 * k2], d1[2 * k2 + 1], a2h[k2], a2l[k2]);

            // L2
            float d2[4][4];
#pragma unroll
            for (int nt = 0; nt < 4; ++nt) dinit(d2[nt], sf, SF_BB2, nt, t);
#pragma unroll
            for (int kt = 0; kt < 4; ++kt)
#pragma unroll
                for (int nt = 0; nt < 4; ++nt) {
                    uint4 bt = *reinterpret_cast<const uint4*>(sb + BW2 + ((kt * 4 + nt) * 32 + lane) * 16);
                    mma3(d2[nt], a2h[kt], a2l[kt], bt);
                }
            // h2e (kept fp32 for residual) ; A3 = h2e
            float h2[4][4];
#pragma unroll
            for (int nt = 0; nt < 4; ++nt)
#pragma unroll
                for (int i = 0; i < 4; ++i) h2[nt][i] = elu1(d2[nt][i]);
            uint32_t a3h[2][4], a3l[2][4];
#pragma unroll
            for (int k2 = 0; k2 < 2; ++k2)
                pack_frag_raw(h2[2 * k2], h2[2 * k2 + 1], a3h[k2], a3l[k2]);

            // t1
            float dt[4][4];
#pragma unroll
            for (int nt = 0; nt < 4; ++nt) dinit(dt[nt], sf, SF_VB1, nt, t);
#pragma unroll
            for (int kt = 0; kt < 2; ++kt)
#pragma unroll
                for (int nt = 0; nt < 4; ++nt) {
                    uint4 bt = *reinterpret_cast<const uint4*>(sb + BV1 + ((kt * 4 + nt) * 32 + lane) * 16);
                    mma3(dt[nt], a3h[kt], a3l[kt], bt);
                }
            uint32_t t1h[2][4], t1l[2][4];
#pragma unroll
            for (int k2 = 0; k2 < 2; ++k2)
                pack_frag_elu(dt[2 * k2], dt[2 * k2 + 1], t1h[k2], t1l[k2]);

            // t2
            float du[4][4];
#pragma unroll
            for (int nt = 0; nt < 4; ++nt) dinit(du[nt], sf, SF_VB2, nt, t);
#pragma unroll
            for (int kt = 0; kt < 2; ++kt)
#pragma unroll
                for (int nt = 0; nt < 4; ++nt) {
                    uint4 bt = *reinterpret_cast<const uint4*>(sb + BV2 + ((kt * 4 + nt) * 32 + lane) * 16);
                    mma3(du[nt], t1h[kt], t1l[kt], bt);
                }
            // x = h2e + elu(t2)
            float xv[4][4];
#pragma unroll
            for (int nt = 0; nt < 4; ++nt)
#pragma unroll
                for (int i = 0; i < 4; ++i) xv[nt][i] = h2[nt][i] + elu1(du[nt][i]);
            uint32_t xh[2][4], xl[2][4];
#pragma unroll
            for (int k2 = 0; k2 < 2; ++k2)
                pack_frag_raw(xv[2 * k2], xv[2 * k2 + 1], xh[k2], xl[k2]);

            // r1 += x @ rw1_v^T
#pragma unroll
            for (int kt = 0; kt < 2; ++kt)
#pragma unroll
                for (int nt = 0; nt < 4; ++nt) {
                    uint4 bt = *reinterpret_cast<const uint4*>(sb + BR1 + ((v * 8 + kt * 4 + nt) * 32 + lane) * 16);
                    mma3(r1d[nt], xh[kt], xl[kt], bt);
                }
        }

        // ---- head ----
        uint32_t rh[2][4], rl[2][4];
#pragma unroll
        for (int k2 = 0; k2 < 2; ++k2)
            pack_frag_elu(r1d[2 * k2], r1d[2 * k2 + 1], rh[k2], rl[k2]);

        float dr[2][4];
#pragma unroll
        for (int nt = 0; nt < 2; ++nt) dinit(dr[nt], sf, SF_RB2, nt, t);
#pragma unroll
        for (int kt = 0; kt < 2; ++kt)
#pragma unroll
            for (int nt = 0; nt < 2; ++nt) {
                uint4 bt = *reinterpret_cast<const uint4*>(sb + BR2 + ((kt * 2 + nt) * 32 + lane) * 16);
                mma3(dr[nt], rh[kt], rl[kt], bt);
            }

        // r2e -> fp32 head scratch [16 pts][16]
#pragma unroll
        for (int nt = 0; nt < 2; ++nt) {
            int bc = nt * 8 + t * 2;
            *reinterpret_cast<float*>(sb + HS + (g * 16 + bc) * 4)       = elu1(dr[nt][0]);
            *reinterpret_cast<float*>(sb + HS + (g * 16 + bc + 1) * 4)   = elu1(dr[nt][1]);
            *reinterpret_cast<float*>(sb + HS + ((g + 8) * 16 + bc) * 4)     = elu1(dr[nt][2]);
            *reinterpret_cast<float*>(sb + HS + ((g + 8) * 16 + bc + 1) * 4) = elu1(dr[nt][3]);
        }
        __syncwarp();
        if (lane < 16) {
            const float* rr = reinterpret_cast<const float*>(sb + HS + lane * 64);
            const int p = tile * 64 + wid * 16 + lane;
#pragma unroll
            for (int c = 0; c < 3; ++c) {
                float a = sf[SF_RB3 + c];
#pragma unroll
                for (int k = 0; k < 16; ++k)
                    a = fmaf(rr[k], sf[SF_RW3 + c * 16 + k], a);
                out_rgb[(size_t)p * 3 + c] = 1.f / (1.f + __expf(-a));
            }
        }
        __syncwarp();
    }
}

extern "C" void kernel_launch(void* const* d_in, const int* in_sizes, int n_in,
                              void* d_out, int out_size)
{
    const float* rgb = (const float*)d_in[0];
    const float* bw1 = (const float*)d_in[1];
    const float* bb1 = (const float*)d_in[2];
    const float* bw2 = (const float*)d_in[3];
    const float* bb2 = (const float*)d_in[4];
    const float* vw1 = (const float*)d_in[5];
    const float* vb1 = (const float*)d_in[6];
    const float* vw2 = (const float*)d_in[7];
    const float* vb2 = (const float*)d_in[8];
    const float* rw1 = (const float*)d_in[9];
    const float* rb1 = (const float*)d_in[10];
    const float* rw2 = (const float*)d_in[11];
    const float* rb2 = (const float*)d_in[12];
    const float* rw3 = (const float*)d_in[13];
    const float* rb3 = (const float*)d_in[14];

    const int P = in_sizes[0] / 105;                  // 524288
    float* out_in  = (float*)d_out;                   // rgb_in : P*9
    float* out_rgb = (float*)d_out + (size_t)P * 9;   // rgb_out: P*3

    // K0: input transpose + rgb_in
    k_prep<<<P / 32, 256>>>(rgb, out_in, P);

    // K1: HMMA fragment-chained MLP (persistent)
    cudaFuncSetAttribute(k_tc, cudaFuncAttributeMaxDynamicSharedMemorySize, SMEM_TC);
    k_tc<<<304, 128, SMEM_TC>>>(
        bw1, bb1, bw2, bb2, vw1, vb1, vw2, vb2,
        rw1, rb1, rw2, rb2, rw3, rb3, out_rgb, P);
}

// round 13
// speedup vs baseline: 4.3895x; 1.1902x over previous
#include <cuda_runtime.h>
#include <cuda_bf16.h>
#include <cstdint>

#define P_CONST 524288

// ---- bias float indices in sf[] ----
#define SF_BB1  0
#define SF_BB2  64
#define SF_VB1  96
#define SF_VB2  128
#define SF_RB1  160
#define SF_RB2  192
#define SF_RW3  208
#define SF_RB3  256

// ---- smem byte offsets (W1A/W1B now live in GLOBAL g_w1) ----
#define BW2  1152u               // 16 tiles (4x4)
#define BV1  (BW2  + 16u*512u)   // 8 tiles  (4x2)
#define BV2  (BV1  +  8u*512u)   // 8 tiles
#define BR1  (BV2  +  8u*512u)   // 24 tiles (3 views x 4x2)
#define BR2  (BR1  + 24u*512u)   // 4 tiles  (2x2)
#define AWBASE (BR2 + 4u*512u)   // per-warp A1 staging, 9216B each
// per warp: A1a hi[16x88 bf16]=2816, A1a lo=2816, A1b hi[16x56]=1792, A1b lo=1792
#define HSBASE (AWBASE + 4u*9216u)   // per-warp head scratch 1024B
#define SMEM_TC (HSBASE + 4u*1024u)  // 72832 B -> 3 CTAs/SM

__device__ float g_scr[(size_t)P_CONST * 105];   // input transposed [P/32][105][32]
__device__ uint4 g_w1[64 * 32];                  // fragment-packed W1A(40 tiles)+W1B(24 tiles)

// ========================= helpers =========================
__device__ __forceinline__ float elu1(float x) {
    return x > 0.f ? x : (__expf(x) - 1.f);
}
__device__ __forceinline__ void bsplit(float x, __nv_bfloat16 &h, __nv_bfloat16 &l) {
    h = __float2bfloat16(x);
    l = __float2bfloat16(x - __bfloat162float(h));
}
__device__ __forceinline__ uint32_t bpack(__nv_bfloat16 a, __nv_bfloat16 b) {
    __nv_bfloat162 t(a, b);    // .x = a = low half
    return *reinterpret_cast<uint32_t*>(&t);
}
// fast pack: two fp32 (cols c,c+1) -> hi/lo bf16x2 regs (6 ops)
__device__ __forceinline__ void pack_hl(float x, float y, uint32_t &hi, uint32_t &lo) {
    asm("cvt.rn.bf16x2.f32 %0, %1, %2;" : "=r"(hi) : "f"(y), "f"(x));   // {y hi, x lo}
    uint32_t hxf = hi << 16;
    uint32_t hyf = hi & 0xFFFF0000u;
    float lx = x - __uint_as_float(hxf);
    float ly = y - __uint_as_float(hyf);
    asm("cvt.rn.bf16x2.f32 %0, %1, %2;" : "=r"(lo) : "f"(ly), "f"(lx));
}

// mma.m16n8k16 row.col f32 += bf16*bf16
__device__ __forceinline__ void mma_bf(float* d, const uint32_t* a, uint32_t b0, uint32_t b1) {
    asm volatile(
        "mma.sync.aligned.m16n8k16.row.col.f32.bf16.bf16.f32 "
        "{%0,%1,%2,%3}, {%4,%5,%6,%7}, {%8,%9}, {%0,%1,%2,%3};"
        : "+f"(d[0]), "+f"(d[1]), "+f"(d[2]), "+f"(d[3])
        : "r"(a[0]), "r"(a[1]), "r"(a[2]), "r"(a[3]), "r"(b0), "r"(b1));
}
// 3-term split product: D += Ah*Bh + Al*Bh + Ah*Bl
__device__ __forceinline__ void mma3(float* d, const uint32_t* ah, const uint32_t* al, uint4 bt) {
    mma_bf(d, ah, bt.x, bt.y);
    mma_bf(d, al, bt.x, bt.y);
    mma_bf(d, ah, bt.z, bt.w);
}
// A fragment from smem bf16 matrix [16 x cols], row stride rs bytes
__device__ __forceinline__ void load_afrag(uint32_t* a, const char* sb, uint32_t base,
                                           int rs, int col0, int g) {
    a[0] = *reinterpret_cast<const uint32_t*>(sb + base + g * rs + col0 * 2);
    a[1] = *reinterpret_cast<const uint32_t*>(sb + base + (g + 8) * rs + col0 * 2);
    a[2] = *reinterpret_cast<const uint32_t*>(sb + base + g * rs + (col0 + 8) * 2);
    a[3] = *reinterpret_cast<const uint32_t*>(sb + base + (g + 8) * rs + (col0 + 8) * 2);
}
__device__ __forceinline__ void dinit(float* d, const float* sf, int boff, int nt, int t) {
    float b0 = sf[boff + nt * 8 + t * 2];
    float b1 = sf[boff + nt * 8 + t * 2 + 1];
    d[0] = b0; d[1] = b1; d[2] = b0; d[3] = b1;
}
__device__ __forceinline__ void pack_frag_elu(const float* dA, const float* dB,
                                              uint32_t* ah, uint32_t* al) {
    pack_hl(elu1(dA[0]), elu1(dA[1]), ah[0], al[0]);
    pack_hl(elu1(dA[2]), elu1(dA[3]), ah[1], al[1]);
    pack_hl(elu1(dB[0]), elu1(dB[1]), ah[2], al[2]);
    pack_hl(elu1(dB[2]), elu1(dB[3]), ah[3], al[3]);
}
__device__ __forceinline__ void pack_frag_raw(const float* dA, const float* dB,
                                              uint32_t* ah, uint32_t* al) {
    pack_hl(dA[0], dA[1], ah[0], al[0]);
    pack_hl(dA[2], dA[3], ah[1], al[1]);
    pack_hl(dB[0], dB[1], ah[2], al[2]);
    pack_hl(dB[2], dB[3], ah[3], al[3]);
}

// stage weight matrix w[N][K] (row stride ldw floats) as fragment-packed B tiles (SMEM)
__device__ void stage_B(char* sb, uint32_t off, const float* __restrict__ w,
                        int N, int K, int ldw, float scale, int NT, int KT,
                        int wid, int lane) {
    int g = lane >> 2, t = lane & 3;
    for (int tile = wid; tile < NT * KT; tile += 4) {
        int kt = tile / NT, nt = tile % NT;
        int n = nt * 8 + g;
        int k0 = kt * 16 + t * 2;
        float v0 = 0.f, v1 = 0.f, v2 = 0.f, v3 = 0.f;
        if (n < N) {
            if (k0 < K)     v0 = __ldg(w + n * ldw + k0) * scale;
            if (k0 + 1 < K) v1 = __ldg(w + n * ldw + k0 + 1) * scale;
            if (k0 + 8 < K) v2 = __ldg(w + n * ldw + k0 + 8) * scale;
            if (k0 + 9 < K) v3 = __ldg(w + n * ldw + k0 + 9) * scale;
        }
        __nv_bfloat16 h0, l0, h1, l1, h2, l2, h3, l3;
        bsplit(v0, h0, l0); bsplit(v1, h1, l1);
        bsplit(v2, h2, l2); bsplit(v3, h3, l3);
        uint4 u;
        u.x = bpack(h0, h1);
        u.y = bpack(h2, h3);
        u.z = bpack(l0, l1);
        u.w = bpack(l2, l3);
        *reinterpret_cast<uint4*>(sb + off + ((uint32_t)tile * 32u + lane) * 16u) = u;
    }
}

// ============== K0a: pack W1A/W1B fragment tiles into global g_w1 ================
__global__ __launch_bounds__(256)
void k_wpack(const float* __restrict__ bw1)
{
    int gid = blockIdx.x * 256 + threadIdx.x;     // 0..2047
    if (gid >= 64 * 32) return;
    int tile = gid >> 5, lane = gid & 31;
    int g = lane >> 2, t = lane & 3;
    const float* w;
    int kt, nt, K;
    if (tile < 40) { kt = tile / 8; nt = tile % 8; w = bw1;      K = 70; }
    else { int u2 = tile - 40; kt = u2 / 8; nt = u2 % 8; w = bw1 + 70; K = 35; }
    int n = nt * 8 + g;
    int k0 = kt * 16 + t * 2;
    float v0 = 0.f, v1 = 0.f, v2 = 0.f, v3 = 0.f;
    if (k0 < K)     v0 = __ldg(w + n * 105 + k0);
    if (k0 + 1 < K) v1 = __ldg(w + n * 105 + k0 + 1);
    if (k0 + 8 < K) v2 = __ldg(w + n * 105 + k0 + 8);
    if (k0 + 9 < K) v3 = __ldg(w + n * 105 + k0 + 9);
    __nv_bfloat16 h0, l0, h1, l1, h2, l2, h3, l3;
    bsplit(v0, h0, l0); bsplit(v1, h1, l1);
    bsplit(v2, h2, l2); bsplit(v3, h3, l3);
    uint4 u;
    u.x = bpack(h0, h1);
    u.y = bpack(h2, h3);
    u.z = bpack(l0, l1);
    u.w = bpack(l2, l3);
    g_w1[tile * 32 + lane] = u;
}

// ================= K0: transpose input to [P/32][105][32] + emit rgb_in ==========
__global__ __launch_bounds__(256, 4)
void k_prep(const float* __restrict__ rgb, float* __restrict__ out_in, int P)
{
    __shared__ float st[32 * 105];
    const int g = blockIdx.x;
    const int tid = threadIdx.x;

    const float4* src4 = reinterpret_cast<const float4*>(rgb + (size_t)g * 3360);
    float4* st4 = reinterpret_cast<float4*>(st);
#pragma unroll
    for (int i = tid; i < 840; i += 256) st4[i] = src4[i];
    __syncthreads();

    float* dst = g_scr + (size_t)g * 3360;
#pragma unroll
    for (int i = tid; i < 3360; i += 256) {
        int j = i >> 5, lane = i & 31;
        dst[i] = st[lane * 105 + j];
    }
    for (int i = tid; i < 288; i += 256) {
        int pl = i / 9, r = i % 9, v = r / 3, k = r % 3;
        out_in[((size_t)g * 32 + pl) * 9 + r] = st[pl * 105 + v * 35 + k];
    }
}

// ====== K1: HMMA fragment-chained MLP, persistent, 3 CTAs/SM (12 warps) ==========
__global__ __launch_bounds__(128, 3)
void k_tc(
    const float* __restrict__ bw1, const float* __restrict__ bb1,
    const float* __restrict__ bw2, const float* __restrict__ bb2,
    const float* __restrict__ vw1, const float* __restrict__ vb1,
    const float* __restrict__ vw2, const float* __restrict__ vb2,
    const float* __restrict__ rw1, const float* __restrict__ rb1,
    const float* __restrict__ rw2, const float* __restrict__ rb2,
    const float* __restrict__ rw3, const float* __restrict__ rb3,
    float* __restrict__ out_rgb, int P)
{
    extern __shared__ char sb[];
    float* sf = reinterpret_cast<float*>(sb);
    const int tid = threadIdx.x;
    const int wid = tid >> 5;
    const int lane = tid & 31;
    const int g = lane >> 2;
    const int t = lane & 3;

    // ---- stage biases ----
    for (int i = tid; i < 64; i += 128) sf[SF_BB1 + i] = bb1[i];
    for (int i = tid; i < 32; i += 128) sf[SF_BB2 + i] = bb2[i];
    for (int i = tid; i < 32; i += 128) sf[SF_VB1 + i] = vb1[i];
    for (int i = tid; i < 32; i += 128) sf[SF_VB2 + i] = vb2[i];
    for (int i = tid; i < 32; i += 128) sf[SF_RB1 + i] = rb1[i];
    for (int i = tid; i < 16; i += 128) sf[SF_RB2 + i] = rb2[i];
    for (int i = tid; i < 48; i += 128) sf[SF_RW3 + i] = rw3[i];
    for (int i = tid; i < 3;  i += 128) sf[SF_RB3 + i] = rb3[i];

    // ---- stage small weights (W1 stays in global g_w1) ----
    stage_B(sb, BW2,  bw2,      32, 64, 64,  1.f,       4, 4, wid, lane);
    stage_B(sb, BV1,  vw1,      32, 32, 32,  1.f / 3.f, 4, 2, wid, lane);
    stage_B(sb, BV2,  vw2,      32, 32, 32,  1.f,       4, 2, wid, lane);
    for (int v = 0; v < 3; ++v)
        stage_B(sb, BR1 + (uint32_t)v * 8u * 512u, rw1 + v * 32, 32, 32, 96, 1.f, 4, 2, wid, lane);
    stage_B(sb, BR2,  rw2,      16, 32, 32,  1.f,       2, 2, wid, lane);

    // per-warp A1 staging bases
    const uint32_t aw   = AWBASE + (uint32_t)wid * 9216u;
    const uint32_t A1AH = aw, A1AL = aw + 2816u;
    const uint32_t A1BH = aw + 5632u, A1BL = aw + 7424u;
    const uint32_t HS   = HSBASE + (uint32_t)wid * 1024u;

    // zero pads: A1a cols 70..79, A1b cols 35..47
    for (int i = lane; i < 160; i += 32) {
        int q = i / 10, c = 70 + i % 10;
        *reinterpret_cast<__nv_bfloat16*>(sb + A1AH + q * 176 + c * 2) = __float2bfloat16(0.f);
        *reinterpret_cast<__nv_bfloat16*>(sb + A1AL + q * 176 + c * 2) = __float2bfloat16(0.f);
    }
    for (int i = lane; i < 208; i += 32) {
        int q = i / 13, c = 35 + i % 13;
        *reinterpret_cast<__nv_bfloat16*>(sb + A1BH + q * 112 + c * 2) = __float2bfloat16(0.f);
        *reinterpret_cast<__nv_bfloat16*>(sb + A1BL + q * 112 + c * 2) = __float2bfloat16(0.f);
    }
    __syncthreads();

    const int ntile = P / 64;
    for (int tile = blockIdx.x; tile < ntile; tile += gridDim.x) {
        const float* gb = g_scr + (size_t)(tile * 2 + (wid >> 1)) * 3360 + (wid & 1) * 16;

        // ---- stats -> A1a (cols 0..34 mean, 35..69 var) ----
        for (int i = lane; i < 560; i += 32) {
            int q = i & 15, k = i >> 4;
            float a = __ldg(gb + k * 32 + q);
            float b = __ldg(gb + (35 + k) * 32 + q);
            float c = __ldg(gb + (70 + k) * 32 + q);
            float m = (a + b + c) * (1.f / 3.f);
            float qv = fmaf(-m, m, fmaf(a, a, fmaf(b, b, c * c)) * (1.f / 3.f));
            __nv_bfloat16 h, l;
            bsplit(m, h, l);
            *reinterpret_cast<__nv_bfloat16*>(sb + A1AH + q * 176 + k * 2) = h;
            *reinterpret_cast<__nv_bfloat16*>(sb + A1AL + q * 176 + k * 2) = l;
            bsplit(qv, h, l);
            *reinterpret_cast<__nv_bfloat16*>(sb + A1AH + q * 176 + (35 + k) * 2) = h;
            *reinterpret_cast<__nv_bfloat16*>(sb + A1AL + q * 176 + (35 + k) * 2) = l;
        }
        __syncwarp();

        // ---- g1 = bb1 + A1a @ W1a^T  (W1a tiles from global, prefetched) ----
        float g1d[8][4];
#pragma unroll
        for (int nt = 0; nt < 8; ++nt) dinit(g1d[nt], sf, SF_BB1, nt, t);
#pragma unroll
        for (int kt = 0; kt < 5; ++kt) {
            uint32_t ah[4], al[4];
            load_afrag(ah, sb, A1AH, 176, kt * 16 + t * 2, g);
            load_afrag(al, sb, A1AL, 176, kt * 16 + t * 2, g);
            uint4 bt[8];
#pragma unroll
            for (int nt = 0; nt < 8; ++nt) bt[nt] = __ldg(&g_w1[(kt * 8 + nt) * 32 + lane]);
#pragma unroll
            for (int nt = 0; nt < 8; ++nt) mma3(g1d[nt], ah, al, bt[nt]);
        }

        float r1d[4][4];
#pragma unroll
        for (int nt = 0; nt < 4; ++nt) dinit(r1d[nt], sf, SF_RB1, nt, t);

        // ---- per-view ----
#pragma unroll 1
        for (int v = 0; v < 3; ++v) {
            // A1b = f_v (cols 0..34)
            for (int i = lane; i < 560; i += 32) {
                int q = i & 15, k = i >> 4;
                float fv = __ldg(gb + (v * 35 + k) * 32 + q);
                __nv_bfloat16 h, l;
                bsplit(fv, h, l);
                *reinterpret_cast<__nv_bfloat16*>(sb + A1BH + q * 112 + k * 2) = h;
                *reinterpret_cast<__nv_bfloat16*>(sb + A1BL + q * 112 + k * 2) = l;
            }
            __syncwarp();

            // L1: d1 = g1 + A1b @ W1b^T  (W1b tiles at g_w1[40..], prefetched)
            float d1[8][4];
#pragma unroll
            for (int nt = 0; nt < 8; ++nt)
#pragma unroll
                for (int i = 0; i < 4; ++i) d1[nt][i] = g1d[nt][i];
#pragma unroll
            for (int kt = 0; kt < 3; ++kt) {
                uint32_t ah[4], al[4];
                load_afrag(ah, sb, A1BH, 112, kt * 16 + t * 2, g);
                load_afrag(al, sb, A1BL, 112, kt * 16 + t * 2, g);
                uint4 bt[8];
#pragma unroll
                for (int nt = 0; nt < 8; ++nt) bt[nt] = __ldg(&g_w1[(40 + kt * 8 + nt) * 32 + lane]);
#pragma unroll
                for (int nt = 0; nt < 8; ++nt) mma3(d1[nt], ah, al, bt[nt]);
            }
            // chain: A2 = elu(d1)
            uint32_t a2h[4][4], a2l[4][4];
#pragma unroll
            for (int k2 = 0; k2 < 4; ++k2)
                pack_frag_elu(d1[2 * k2], d1[2 * k2 + 1], a2h[k2], a2l[k2]);

            // L2
            float d2[4][4];
#pragma unroll
            for (int nt = 0; nt < 4; ++nt) dinit(d2[nt], sf, SF_BB2, nt, t);
#pragma unroll
            for (int kt = 0; kt < 4; ++kt)
#pragma unroll
                for (int nt = 0; nt < 4; ++nt) {
                    uint4 bt = *reinterpret_cast<const uint4*>(sb + BW2 + ((kt * 4 + nt) * 32 + lane) * 16);
                    mma3(d2[nt], a2h[kt], a2l[kt], bt);
                }
            float h2[4][4];
#pragma unroll
            for (int nt = 0; nt < 4; ++nt)
#pragma unroll
                for (int i = 0; i < 4; ++i) h2[nt][i] = elu1(d2[nt][i]);
            uint32_t a3h[2][4], a3l[2][4];
#pragma unroll
            for (int k2 = 0; k2 < 2; ++k2)
                pack_frag_raw(h2[2 * k2], h2[2 * k2 + 1], a3h[k2], a3l[k2]);

            // t1
            float dt[4][4];
#pragma unroll
            for (int nt = 0; nt < 4; ++nt) dinit(dt[nt], sf, SF_VB1, nt, t);
#pragma unroll
            for (int kt = 0; kt < 2; ++kt)
#pragma unroll
                for (int nt = 0; nt < 4; ++nt) {
                    uint4 bt = *reinterpret_cast<const uint4*>(sb + BV1 + ((kt * 4 + nt) * 32 + lane) * 16);
                    mma3(dt[nt], a3h[kt], a3l[kt], bt);
                }
            uint32_t t1h[2][4], t1l[2][4];
#pragma unroll
            for (int k2 = 0; k2 < 2; ++k2)
                pack_frag_elu(dt[2 * k2], dt[2 * k2 + 1], t1h[k2], t1l[k2]);

            // t2
            float du[4][4];
#pragma unroll
            for (int nt = 0; nt < 4; ++nt) dinit(du[nt], sf, SF_VB2, nt, t);
#pragma unroll
            for (int kt = 0; kt < 2; ++kt)
#pragma unroll
                for (int nt = 0; nt < 4; ++nt) {
                    uint4 bt = *reinterpret_cast<const uint4*>(sb + BV2 + ((kt * 4 + nt) * 32 + lane) * 16);
                    mma3(du[nt], t1h[kt], t1l[kt], bt);
                }
            // x = h2e + elu(t2)
            float xv[4][4];
#pragma unroll
            for (int nt = 0; nt < 4; ++nt)
#pragma unroll
                for (int i = 0; i < 4; ++i) xv[nt][i] = h2[nt][i] + elu1(du[nt][i]);
            uint32_t xh[2][4], xl[2][4];
#pragma unroll
            for (int k2 = 0; k2 < 2; ++k2)
                pack_frag_raw(xv[2 * k2], xv[2 * k2 + 1], xh[k2], xl[k2]);

            // r1 += x @ rw1_v^T
#pragma unroll
            for (int kt = 0; kt < 2; ++kt)
#pragma unroll
                for (int nt = 0; nt < 4; ++nt) {
                    uint4 bt = *reinterpret_cast<const uint4*>(sb + BR1 + ((v * 8 + kt * 4 + nt) * 32 + lane) * 16);
                    mma3(r1d[nt], xh[kt], xl[kt], bt);
                }
        }

        // ---- head ----
        uint32_t rh[2][4], rl[2][4];
#pragma unroll
        for (int k2 = 0; k2 < 2; ++k2)
            pack_frag_elu(r1d[2 * k2], r1d[2 * k2 + 1], rh[k2], rl[k2]);

        float dr[2][4];
#pragma unroll
        for (int nt = 0; nt < 2; ++nt) dinit(dr[nt], sf, SF_RB2, nt, t);
#pragma unroll
        for (int kt = 0; kt < 2; ++kt)
#pragma unroll
            for (int nt = 0; nt < 2; ++nt) {
                uint4 bt = *reinterpret_cast<const uint4*>(sb + BR2 + ((kt * 2 + nt) * 32 + lane) * 16);
                mma3(dr[nt], rh[kt], rl[kt], bt);
            }

        // r2e -> fp32 head scratch [16 pts][16]
#pragma unroll
        for (int nt = 0; nt < 2; ++nt) {
            int bc = nt * 8 + t * 2;
            *reinterpret_cast<float*>(sb + HS + (g * 16 + bc) * 4)           = elu1(dr[nt][0]);
            *reinterpret_cast<float*>(sb + HS + (g * 16 + bc + 1) * 4)       = elu1(dr[nt][1]);
            *reinterpret_cast<float*>(sb + HS + ((g + 8) * 16 + bc) * 4)     = elu1(dr[nt][2]);
            *reinterpret_cast<float*>(sb + HS + ((g + 8) * 16 + bc + 1) * 4) = elu1(dr[nt][3]);
        }
        __syncwarp();
        if (lane < 16) {
            const float* rr = reinterpret_cast<const float*>(sb + HS + lane * 64);
            const int p = tile * 64 + wid * 16 + lane;
#pragma unroll
            for (int c = 0; c < 3; ++c) {
                float a = sf[SF_RB3 + c];
#pragma unroll
                for (int k = 0; k < 16; ++k)
                    a = fmaf(rr[k], sf[SF_RW3 + c * 16 + k], a);
                out_rgb[(size_t)p * 3 + c] = 1.f / (1.f + __expf(-a));
            }
        }
        __syncwarp();
    }
}

extern "C" void kernel_launch(void* const* d_in, const int* in_sizes, int n_in,
                              void* d_out, int out_size)
{
    const float* rgb = (const float*)d_in[0];
    const float* bw1 = (const float*)d_in[1];
    const float* bb1 = (const float*)d_in[2];
    const float* bw2 = (const float*)d_in[3];
    const float* bb2 = (const float*)d_in[4];
    const float* vw1 = (const float*)d_in[5];
    const float* vb1 = (const float*)d_in[6];
    const float* vw2 = (const float*)d_in[7];
    const float* vb2 = (const float*)d_in[8];
    const float* rw1 = (const float*)d_in[9];
    const float* rb1 = (const float*)d_in[10];
    const float* rw2 = (const float*)d_in[11];
    const float* rb2 = (const float*)d_in[12];
    const float* rw3 = (const float*)d_in[13];
    const float* rb3 = (const float*)d_in[14];

    const int P = in_sizes[0] / 105;                  // 524288
    float* out_in  = (float*)d_out;                   // rgb_in : P*9
    float* out_rgb = (float*)d_out + (size_t)P * 9;   // rgb_out: P*3

    // K0a: pack W1 fragment tiles into global
    k_wpack<<<8, 256>>>(bw1);
    // K0: input transpose + rgb_in
    k_prep<<<P / 32, 256>>>(rgb, out_in, P);

    // K1: HMMA fragment-chained MLP (persistent, 3 CTAs/SM)
    cudaFuncSetAttribute(k_tc, cudaFuncAttributeMaxDynamicSharedMemorySize, SMEM_TC);
    k_tc<<<456, 128, SMEM_TC>>>(
        bw1, bb1, bw2, bb2, vw1, vb1, vw2, vb2,
        rw1, rb1, rw2, rb2, rw3, rb3, out_rgb, P);
}